// round 16
// baseline (speedup 1.0000x reference)
#include <cuda_runtime.h>
#include <cstddef>

// Problem constants
#define BB 8
#define CC 2
#define DIN 96
#define HIN 64
#define WIN 64
#define FF 8
#define DD 3
#define HH 60
#define WW 64
#define DOUT 94        // 96 - 3 + 1
#define TT 4           // t-group size
#define NTG 24         // ceil(94/4)
#define LEAKY 0.2f

// Input staging: [c][zi][r in 0..35][64 cols] float, r -> input row y0-1+r
#define NROWS 36
#define STAGE_FLOATS (CC * (TT + 2) * NROWS * 64)   // 27648 floats = 110.6 KB
// H buffer: 2 bufs x TT x 32 rows x 64 cols, ALIASES the staging region
#define BUFSTRIDE (TT * 32 * 64)          // 8192 floats per buffer
#define H_FLOATS (2 * BUFSTRIDE)          // 16384 floats <= STAGE_FLOATS
#define SMEM_FLOATS STAGE_FLOATS
#define OUT_FSTRIDE (DOUT * HH * WW)      // out advance per f
#define BC_FSTRIDE (HH * WW)              // g_Bc advance per f
#define W_FSTRIDE (CC * DD * HH * WW)     // weight advance per f

// Precomputed bias box-sum, pre-scaled by 0.25:
// Bc[f][y][x] = 0.25 * sum over c,dd and valid 3x3 window of bias
__device__ float g_Bc[FF * HH * WW];

// Grid (FF, 15): block (f, g) computes rows y in [4g, 4g+4). Haloed fold rows in smem.
__global__ __launch_bounds__(256) void bconv_kernel(const float* __restrict__ bias) {
    __shared__ float P[6][66];            // fold rows 4g-1 .. 4g+4, cols padded
    const int f = blockIdx.x;
    const int g = blockIdx.y;
    const int tid = threadIdx.x;
    for (int i = tid; i < 6 * 66; i += 256) (&P[0][0])[i] = 0.f;
    __syncthreads();
    for (int idx = tid; idx < 6 * 64; idx += 256) {
        int x = idx & 63, row = idx >> 6;
        int yy = 4 * g - 1 + row;
        if (yy >= 0 && yy < HH) {
            float s = 0.f;
            #pragma unroll
            for (int c = 0; c < CC; c++)
                #pragma unroll
                for (int dd = 0; dd < DD; dd++)
                    s += bias[(((f * CC + c) * DD + dd) * HH + yy) * WW + x];
            P[row][x + 1] = s;
        }
    }
    __syncthreads();
    for (int idx = tid; idx < 4 * 64; idx += 256) {
        int x = idx & 63, r = idx >> 6;
        int y = 4 * g + r;                // always < 60 (15*4 = 60 exact)
        float s = P[r][x]     + P[r][x + 1]     + P[r][x + 2]
                + P[r + 1][x] + P[r + 1][x + 1] + P[r + 1][x + 2]
                + P[r + 2][x] + P[r + 2][x + 1] + P[r + 2][x + 2];
        g_Bc[(f * HH + y) * WW + x] = 0.25f * s;
    }
}

// Load 6 weight float2's from a per-thread base pointer (advanced by W_FSTRIDE per f).
__device__ __forceinline__ void load_W(float2 (&Wr)[CC][DD],
                                       const float* __restrict__ wp, bool vrow) {
    if (!vrow) return;
    #pragma unroll
    for (int c = 0; c < CC; c++)
        #pragma unroll
        for (int dd = 0; dd < DD; dd++)
            Wr[c][dd] = *(const float2*)(wp + (c * DD + dd) * (HH * WW));
}

// Build T for one f (S pre-scaled by 0.25), horizontally fold via warp shuffles,
// store H to smem AND keep this thread's own H values in registers.
__device__ __forceinline__ void build_store(float* __restrict__ hdst,
                                            float2 (&Hreg)[TT],
                                            const float2 (&Wr)[CC][DD],
                                            const float2 (&S)[CC][TT + 2],
                                            int xi, bool vrow) {
    #pragma unroll
    for (int t = 0; t < TT; t++) Hreg[t] = make_float2(0.f, 0.f);
    if (!vrow) return;
    #pragma unroll
    for (int t = 0; t < TT; t++) {
        float2 a = make_float2(0.f, 0.f);
        #pragma unroll
        for (int c = 0; c < CC; c++) {
            #pragma unroll
            for (int dd = 0; dd < DD; dd++) {
                a.x = fmaf(S[c][t + dd].x, Wr[c][dd].x, a.x);
                a.y = fmaf(S[c][t + dd].y, Wr[c][dd].y, a.y);
            }
        }
        // horizontal 3-tap fold: h[x] = T[x-1]+T[x]+T[x+1], SAME zero pad at edges
        float left  = __shfl_up_sync(0xffffffffu, a.y, 1);
        float right = __shfl_down_sync(0xffffffffu, a.x, 1);
        if (xi == 0)  left  = 0.f;
        if (xi == 31) right = 0.f;
        float mid = a.x + a.y;
        float2 h = make_float2(left + mid, mid + right);
        Hreg[t] = h;
        *(float2*)(hdst + t * (32 * 64)) = h;
    }
}

// Main fused kernel, software-pipelined over f with double-buffered H.
// Grid: x = tg*2 + half (48), y = b (8). Block: 1024 threads = 32 warps.
// Prologue: stage the CTA's raw input window (c,zi,36 rows,64 cols) into smem
// with one coalesced LDG pass (4.4x less L2 traffic than direct S loads), then
// build register S via LDS. The H double-buffer aliases the staging region
// after a barrier.
// Build: thread (ty=tid/32, xi=tid%32) owns T-row ys=y0-1+ty, cols [2xi, 2xi+2).
// Consume: thread ty in [1,30] outputs row yo=ys at its own columns (float2):
//   out = leaky(Hreg + H[ty-1] + H[ty+1] + bc)  (0.25 pre-folded into S and Bc).
__global__ __launch_bounds__(1024, 1)
void linconv_main(const float* __restrict__ in,
                  const float* __restrict__ wgt,
                  float* __restrict__ out) {
    extern __shared__ float smem[];

    const int b     = blockIdx.y;
    const int tg    = blockIdx.x >> 1;
    const int half  = blockIdx.x & 1;
    const int tbase = tg * TT;
    const int tcnt  = min(TT, DOUT - tbase);
    const int y0    = half * 30;
    const int tid   = threadIdx.x;
    const int ty    = tid >> 5;
    const int xi    = tid & 31;
    const int x     = xi * 2;
    const int ys    = y0 - 1 + ty;                    // T row this thread builds
    const bool vrow = (ys >= 0 && ys < HH);
    const bool cons = (ty >= 1 && ty <= 30);          // warp-uniform consume predicate

    // ---- stage input window into smem (zeros for out-of-range y/z) ----
    {
        const int nf2 = STAGE_FLOATS / 2;             // 13824 float2 items
        #pragma unroll
        for (int i = 0; i < (nf2 + 1023) / 1024; i++) {
            int idx = tid + i * 1024;
            if (idx < nf2) {
                int xp   = idx & 31;
                int rest = idx >> 5;
                int r    = rest % NROWS;
                int czi  = rest / NROWS;              // 0..11
                int zi   = czi % (TT + 2);
                int c    = czi / (TT + 2);
                int y    = y0 - 1 + r;
                int z    = tbase + zi;
                float2 v = make_float2(0.f, 0.f);
                if (y >= 0 && y < HIN && z < DIN)
                    v = *(const float2*)(in + (((size_t)(b * CC + c) * DIN + z) * HIN + y) * WIN + 2 * xp);
                *(float2*)(smem + idx * 2) = v;
            }
        }
    }
    __syncthreads();

    // S[c][zi] = 0.25 * (5-row vertical sum), read from staged smem (rows ty..ty+4)
    float2 S[CC][TT + 2];
    #pragma unroll
    for (int c = 0; c < CC; c++) {
        #pragma unroll
        for (int zi = 0; zi < TT + 2; zi++) {
            const float* base = smem + ((c * (TT + 2) + zi) * NROWS + ty) * 64 + x;
            float2 s = make_float2(0.f, 0.f);
            #pragma unroll
            for (int j = 0; j < 5; j++) {
                float2 v = *(const float2*)(base + j * 64);
                s.x += v.x; s.y += v.y;
            }
            s.x *= 0.25f; s.y *= 0.25f;
            S[c][zi] = s;
        }
    }
    __syncthreads();          // all staging reads done; H region may now be written

    float* const hbase = smem + ty * 64 + x;          // build dst, + buf*BUFSTRIDE

    // Zero ONLY the rows build never writes (edge rows with !vrow): they act as
    // the vertical SAME pad. All other rows are rewritten by build before any read.
    if (!vrow) {
        #pragma unroll
        for (int t = 0; t < TT; t++) {
            *(float2*)(hbase + t * (32 * 64)) = make_float2(0.f, 0.f);
            *(float2*)(hbase + BUFSTRIDE + t * (32 * 64)) = make_float2(0.f, 0.f);
        }
    }

    // ---- fixed consume pointers (advanced per f) ----
    const float* bcp = g_Bc + ys * WW + x;            // t-invariant, yo = ys
    float* outp = out + ((((size_t)b * FF) * DOUT + tbase) * HH + ys) * WW + x;
    const float* const hTop = smem + (ty - 1) * 64 + x;
    const float* const hBot = smem + (ty + 1) * 64 + x;

    // per-thread weight base pointer (advanced per f)
    const float* wp = wgt + ys * WW + x;

    // prologue: weights + build for f=0 into buffer 0
    float2 Wr[CC][DD];
    float2 Hreg[TT];
    load_W(Wr, wp, vrow);
    build_store(hbase, Hreg, Wr, S, xi, vrow);
    __syncthreads();

    #pragma unroll 1
    for (int f = 0; f < FF; f++) {
        const int cur = f & 1;
        const bool more = (f + 1 < FF);

        // prefetch next-f weights into registers (latency drains behind consume)
        if (more) load_W(Wr, wp + (f + 1) * W_FSTRIDE, vrow);

        // ---- consume phase: own-row H (regs) + neighbor rows (smem) + bias ----
        if (cons) {
            float2 bc = *(const float2*)bcp;
            const size_t bo = (size_t)cur * BUFSTRIDE;
            #pragma unroll
            for (int t = 0; t < TT; t++) {
                if (t < tcnt) {
                    float2 rt = *(const float2*)(hTop + bo + t * (32 * 64));
                    float2 rb = *(const float2*)(hBot + bo + t * (32 * 64));
                    float o0 = rt.x + Hreg[t].x + rb.x + bc.x;
                    float o1 = rt.y + Hreg[t].y + rb.y + bc.y;
                    o0 = (o0 > 0.f) ? o0 : LEAKY * o0;
                    o1 = (o1 > 0.f) ? o1 : LEAKY * o1;
                    *(float2*)(outp + t * (HH * WW)) = make_float2(o0, o1);
                }
            }
        }
        bcp  += BC_FSTRIDE;
        outp += OUT_FSTRIDE;

        // ---- build phase for f+1 into the other buffer (W already in registers) ----
        if (more)
            build_store(hbase + (cur ^ 1) * BUFSTRIDE, Hreg, Wr, S, xi, vrow);

        __syncthreads();
    }
}

extern "C" void kernel_launch(void* const* d_in, const int* in_sizes, int n_in,
                              void* d_out, int out_size) {
    const float* in   = (const float*)d_in[0];
    const float* wgt  = (const float*)d_in[1];
    const float* bias = (const float*)d_in[2];
    float* out        = (float*)d_out;

    static bool attr_set = false;
    if (!attr_set) {
        cudaFuncSetAttribute(linconv_main,
                             cudaFuncAttributeMaxDynamicSharedMemorySize,
                             SMEM_FLOATS * sizeof(float));
        attr_set = true;
    }

    dim3 bgrid(FF, 15);
    bconv_kernel<<<bgrid, 256>>>(bias);

    dim3 grid(NTG * 2, BB);
    linconv_main<<<grid, 1024, SMEM_FLOATS * sizeof(float)>>>(in, wgt, out);
}

// round 17
// speedup vs baseline: 1.7910x; 1.7910x over previous
#include <cuda_runtime.h>
#include <cstddef>

// Problem constants
#define BB 8
#define CC 2
#define DIN 96
#define HIN 64
#define WIN 64
#define FF 8
#define DD 3
#define HH 60
#define WW 64
#define DOUT 94        // 96 - 3 + 1
#define TT 4           // t-group size
#define NTG 24         // ceil(94/4)
#define LEAKY 0.2f

// H buffer: 2 bufs x TT x 32 rows x 64 cols (horizontally-folded T)
#define BUFSTRIDE (TT * 32 * 64)          // 8192 floats per buffer
#define SMEM_FLOATS (2 * BUFSTRIDE)
#define OUT_FSTRIDE (DOUT * HH * WW)      // out advance per f
#define BC_FSTRIDE (HH * WW)              // g_Bc advance per f
#define W_FSTRIDE (CC * DD * HH * WW)     // weight advance per f

// Precomputed bias box-sum, pre-scaled by 0.25:
// Bc[f][y][x] = 0.25 * sum over c,dd and valid 3x3 window of bias
__device__ float g_Bc[FF * HH * WW];

// Grid (FF, 15): block (f, g) computes rows y in [4g, 4g+4). Haloed fold rows in smem.
__global__ __launch_bounds__(256) void bconv_kernel(const float* __restrict__ bias) {
    __shared__ float P[6][66];            // fold rows 4g-1 .. 4g+4, cols padded
    const int f = blockIdx.x;
    const int g = blockIdx.y;
    const int tid = threadIdx.x;
    for (int i = tid; i < 6 * 66; i += 256) (&P[0][0])[i] = 0.f;
    __syncthreads();
    for (int idx = tid; idx < 6 * 64; idx += 256) {
        int x = idx & 63, row = idx >> 6;
        int yy = 4 * g - 1 + row;
        if (yy >= 0 && yy < HH) {
            float s = 0.f;
            #pragma unroll
            for (int c = 0; c < CC; c++)
                #pragma unroll
                for (int dd = 0; dd < DD; dd++)
                    s += bias[(((f * CC + c) * DD + dd) * HH + yy) * WW + x];
            P[row][x + 1] = s;
        }
    }
    __syncthreads();
    for (int idx = tid; idx < 4 * 64; idx += 256) {
        int x = idx & 63, r = idx >> 6;
        int y = 4 * g + r;                // always < 60 (15*4 = 60 exact)
        float s = P[r][x]     + P[r][x + 1]     + P[r][x + 2]
                + P[r + 1][x] + P[r + 1][x + 1] + P[r + 1][x + 2]
                + P[r + 2][x] + P[r + 2][x + 1] + P[r + 2][x + 2];
        g_Bc[(f * HH + y) * WW + x] = 0.25f * s;
    }
}

// Load 6 weight float2's from a per-thread base pointer (advanced by W_FSTRIDE per f).
__device__ __forceinline__ void load_W(float2 (&Wr)[CC][DD],
                                       const float* __restrict__ wp, bool vrow) {
    if (!vrow) return;
    #pragma unroll
    for (int c = 0; c < CC; c++)
        #pragma unroll
        for (int dd = 0; dd < DD; dd++)
            Wr[c][dd] = *(const float2*)(wp + (c * DD + dd) * (HH * WW));
}

// Build T for one f (S pre-scaled by 0.25), horizontally fold via warp shuffles,
// store H to smem AND keep this thread's own H values in registers.
__device__ __forceinline__ void build_store(float* __restrict__ hdst,
                                            float2 (&Hreg)[TT],
                                            const float2 (&Wr)[CC][DD],
                                            const float2 (&S)[CC][TT + 2],
                                            int xi, bool vrow) {
    #pragma unroll
    for (int t = 0; t < TT; t++) Hreg[t] = make_float2(0.f, 0.f);
    if (!vrow) return;
    #pragma unroll
    for (int t = 0; t < TT; t++) {
        float2 a = make_float2(0.f, 0.f);
        #pragma unroll
        for (int c = 0; c < CC; c++) {
            #pragma unroll
            for (int dd = 0; dd < DD; dd++) {
                a.x = fmaf(S[c][t + dd].x, Wr[c][dd].x, a.x);
                a.y = fmaf(S[c][t + dd].y, Wr[c][dd].y, a.y);
            }
        }
        // horizontal 3-tap fold: h[x] = T[x-1]+T[x]+T[x+1], SAME zero pad at edges
        float left  = __shfl_up_sync(0xffffffffu, a.y, 1);
        float right = __shfl_down_sync(0xffffffffu, a.x, 1);
        if (xi == 0)  left  = 0.f;
        if (xi == 31) right = 0.f;
        float mid = a.x + a.y;
        float2 h = make_float2(left + mid, mid + right);
        Hreg[t] = h;
        *(float2*)(hdst + t * (32 * 64)) = h;
    }
}

// Main fused kernel, software-pipelined over f with double-buffered H.
// Grid: x = tg*2 + half (48), y = b (8). Block: 1024 threads = 32 warps.
// Build: thread (ty=tid/32, xi=tid%32) owns T-row ys=y0-1+ty, cols [2xi, 2xi+2).
// Consume: thread ty in [1,30] outputs row yo=ys at its own columns (float2):
//   out = leaky(Hreg + H[ty-1] + H[ty+1] + bc)  (0.25 pre-folded into S and Bc).
// Output uses streaming (.cs) stores: write-once data, keep it out of L2.
__global__ __launch_bounds__(1024, 1)
void linconv_main(const float* __restrict__ in,
                  const float* __restrict__ wgt,
                  float* __restrict__ out) {
    extern __shared__ float smem[];

    const int b     = blockIdx.y;
    const int tg    = blockIdx.x >> 1;
    const int half  = blockIdx.x & 1;
    const int tbase = tg * TT;
    const int tcnt  = min(TT, DOUT - tbase);
    const int y0    = half * 30;
    const int tid   = threadIdx.x;
    const int ty    = tid >> 5;
    const int xi    = tid & 31;
    const int x     = xi * 2;
    const int ys    = y0 - 1 + ty;                    // T row this thread builds
    const bool vrow = (ys >= 0 && ys < HH);
    const bool cons = (ty >= 1 && ty <= 30);          // warp-uniform consume predicate

    float* const hbase = smem + ty * 64 + x;          // build dst, + buf*BUFSTRIDE

    // Zero ONLY the rows build never writes (edge rows with !vrow): they act as
    // the vertical SAME pad. All other rows are rewritten by build before any read.
    if (!vrow) {
        #pragma unroll
        for (int t = 0; t < TT; t++) {
            *(float2*)(hbase + t * (32 * 64)) = make_float2(0.f, 0.f);
            *(float2*)(hbase + BUFSTRIDE + t * (32 * 64)) = make_float2(0.f, 0.f);
        }
    }

    // S[c][zi] = 0.25 * (5-row vertical sum of input), pre-scaled once
    float2 S[CC][TT + 2];
    #pragma unroll
    for (int c = 0; c < CC; c++) {
        #pragma unroll
        for (int zi = 0; zi < TT + 2; zi++) {
            float2 s = make_float2(0.f, 0.f);
            if (vrow && zi < tcnt + 2) {
                const float* p = in + (((size_t)(b * CC + c) * DIN + (tbase + zi)) * HIN + ys) * WIN + x;
                #pragma unroll
                for (int j = 0; j < 5; j++) {
                    float2 v = *(const float2*)(p + j * WIN);
                    s.x += v.x; s.y += v.y;
                }
                s.x *= 0.25f; s.y *= 0.25f;
            }
            S[c][zi] = s;
        }
    }

    // ---- fixed consume pointers (advanced per f) ----
    const float* bcp = g_Bc + ys * WW + x;            // t-invariant, yo = ys
    float* outp = out + ((((size_t)b * FF) * DOUT + tbase) * HH + ys) * WW + x;
    const float* const hTop = smem + (ty - 1) * 64 + x;
    const float* const hBot = smem + (ty + 1) * 64 + x;

    // per-thread weight base pointer (advanced per f)
    const float* wp = wgt + ys * WW + x;

    // prologue: weights + build for f=0 into buffer 0
    float2 Wr[CC][DD];
    float2 Hreg[TT];
    load_W(Wr, wp, vrow);
    __syncthreads();          // edge-row zeroing complete before first build/consume
    build_store(hbase, Hreg, Wr, S, xi, vrow);
    __syncthreads();

    #pragma unroll 1
    for (int f = 0; f < FF; f++) {
        const int cur = f & 1;
        const bool more = (f + 1 < FF);

        // bc load hoisted to iteration top: its L2 latency overlaps the W prefetch
        float2 bc = make_float2(0.f, 0.f);
        if (cons) bc = *(const float2*)bcp;

        // prefetch next-f weights into registers (latency drains behind consume)
        if (more) load_W(Wr, wp + (f + 1) * W_FSTRIDE, vrow);

        // ---- consume phase: own-row H (regs) + neighbor rows (smem) + bias ----
        if (cons) {
            const size_t bo = (size_t)cur * BUFSTRIDE;
            #pragma unroll
            for (int t = 0; t < TT; t++) {
                if (t < tcnt) {
                    float2 rt = *(const float2*)(hTop + bo + t * (32 * 64));
                    float2 rb = *(const float2*)(hBot + bo + t * (32 * 64));
                    float o0 = rt.x + Hreg[t].x + rb.x + bc.x;
                    float o1 = rt.y + Hreg[t].y + rb.y + bc.y;
                    o0 = (o0 > 0.f) ? o0 : LEAKY * o0;
                    o1 = (o1 > 0.f) ? o1 : LEAKY * o1;
                    __stcs((float2*)(outp + t * (HH * WW)), make_float2(o0, o1));
                }
            }
        }
        bcp  += BC_FSTRIDE;
        outp += OUT_FSTRIDE;

        // ---- build phase for f+1 into the other buffer (W already in registers) ----
        if (more)
            build_store(hbase + (cur ^ 1) * BUFSTRIDE, Hreg, Wr, S, xi, vrow);

        __syncthreads();
    }
}

extern "C" void kernel_launch(void* const* d_in, const int* in_sizes, int n_in,
                              void* d_out, int out_size) {
    const float* in   = (const float*)d_in[0];
    const float* wgt  = (const float*)d_in[1];
    const float* bias = (const float*)d_in[2];
    float* out        = (float*)d_out;

    static bool attr_set = false;
    if (!attr_set) {
        cudaFuncSetAttribute(linconv_main,
                             cudaFuncAttributeMaxDynamicSharedMemorySize,
                             SMEM_FLOATS * sizeof(float));
        attr_set = true;
    }

    dim3 bgrid(FF, 15);
    bconv_kernel<<<bgrid, 256>>>(bias);

    dim3 grid(NTG * 2, BB);
    linconv_main<<<grid, 1024, SMEM_FLOATS * sizeof(float)>>>(in, wgt, out);
}